// round 10
// baseline (speedup 1.0000x reference)
#include <cuda_runtime.h>
#include <cuda_fp16.h>
#include <cstdint>

#define N_NODES 100000
#define D 128
#define MAXE 2000000

// ---------------- device scratch (no allocations allowed) -------------------
__device__ __half g_xh  [N_NODES * D];    // fp16 copy of x
__device__ __half g_agg [N_NODES * D];    // aggregated means (fp16)
__device__ __half g_h1  [N_NODES * D];    // layer-1 activations (fp16)
__device__ __half g_h2  [N_NODES * D];    // layer-2 activations (fp16)
__device__ __half g_tmp [N_NODES * D];    // right-branch GEMM result (fp16)
__device__ int    g_cnt[N_NODES];         // degree histogram (re-zeroed by scan)
__device__ int    g_rowstart[N_NODES + 1];
__device__ int    g_cursor[N_NODES];
__device__ int    g_perm[MAXE];           // dst-sorted src indices

// ---------------------------------------------------------------------------
// prep: convert x -> fp16 AND histogram dst degrees (fused, one launch)
// ---------------------------------------------------------------------------
__global__ void k_prep(const float* __restrict__ x, const int* __restrict__ dst,
                       __half* __restrict__ xh, int* __restrict__ cnt,
                       int E, int n8) {
    int i = blockIdx.x * blockDim.x + threadIdx.x;
    if (i < n8) {
        const float4* xp = (const float4*)x + (size_t)i * 2;
        float4 v0 = xp[0], v1 = xp[1];
        __half2 p0 = __floats2half2_rn(v0.x, v0.y);
        __half2 p1 = __floats2half2_rn(v0.z, v0.w);
        __half2 p2 = __floats2half2_rn(v1.x, v1.y);
        __half2 p3 = __floats2half2_rn(v1.z, v1.w);
        uint4 w;
        w.x = *(uint32_t*)&p0; w.y = *(uint32_t*)&p1;
        w.z = *(uint32_t*)&p2; w.w = *(uint32_t*)&p3;
        ((uint4*)xh)[i] = w;
    }
    if (i < E) atomicAdd(cnt + __ldg(dst + i), 1);
}

// ---------------------------------------------------------------------------
// Coalesced single-block scan (warp-shuffle); re-zeroes cnt for graph replay.
// ---------------------------------------------------------------------------
__global__ void __launch_bounds__(1024) k_scan(int* __restrict__ cnt,
                                               int* __restrict__ rowstart,
                                               int* __restrict__ cursor, int E) {
    __shared__ int wsum[32];
    const int t    = threadIdx.x;
    const int lane = t & 31;
    const int wid  = t >> 5;
    int carry = 0;
    for (int base = 0; base < N_NODES; base += 1024) {
        int i = base + t;
        int v = (i < N_NODES) ? cnt[i] : 0;
        int s = v;
        #pragma unroll
        for (int off = 1; off < 32; off <<= 1) {
            int u = __shfl_up_sync(0xffffffffu, s, off);
            if (lane >= off) s += u;
        }
        if (lane == 31) wsum[wid] = s;
        __syncthreads();
        if (wid == 0) {
            int w = wsum[lane];
            #pragma unroll
            for (int off = 1; off < 32; off <<= 1) {
                int u = __shfl_up_sync(0xffffffffu, w, off);
                if (lane >= off) w += u;
            }
            wsum[lane] = w;
        }
        __syncthreads();
        int wofs = (wid > 0) ? wsum[wid - 1] : 0;
        int excl = carry + wofs + (s - v);
        if (i < N_NODES) {
            rowstart[i] = excl;
            cursor[i]   = excl;
            cnt[i]      = 0;
        }
        int tot = wsum[31];
        __syncthreads();
        carry += tot;
    }
    if (t == 0) rowstart[N_NODES] = E;
}

// ---------------------------------------------------------------------------
__global__ void k_permute(const int* __restrict__ src, const int* __restrict__ dst,
                          int* __restrict__ cursor, int* __restrict__ perm, int E) {
    int e = blockIdx.x * blockDim.x + threadIdx.x;
    if (e < E) {
        int pos = atomicAdd(cursor + __ldg(dst + e), 1);
        perm[pos] = __ldg(src + e);
    }
}

// ---------------------------------------------------------------------------
// CSR gather-mean over fp16 rows (measured 41.5us)
// ---------------------------------------------------------------------------
__device__ __forceinline__ void acc4(float4& a, uint2 u) {
    __half2 h0 = *(__half2*)&u.x, h1 = *(__half2*)&u.y;
    float2 f0 = __half22float2(h0), f1 = __half22float2(h1);
    a.x += f0.x; a.y += f0.y; a.z += f1.x; a.w += f1.y;
}

__global__ void __launch_bounds__(256)
k_gather(const __half* __restrict__ xh, const int* __restrict__ perm,
         const int* __restrict__ rowstart, __half* __restrict__ agg) {
    int node = blockIdx.x * 8 + (threadIdx.x >> 5);
    int lane = threadIdx.x & 31;
    if (node >= N_NODES) return;
    int beg = __ldg(rowstart + node);
    int end = __ldg(rowstart + node + 1);
    const uint2* xp = (const uint2*)xh;
    float4 acc = make_float4(0.f, 0.f, 0.f, 0.f);
    int i = beg;
    for (; i + 4 <= end; i += 4) {
        int s0 = __ldg(perm + i),     s1 = __ldg(perm + i + 1);
        int s2 = __ldg(perm + i + 2), s3 = __ldg(perm + i + 3);
        uint2 u0 = __ldg(xp + (size_t)s0 * 32 + lane);
        uint2 u1 = __ldg(xp + (size_t)s1 * 32 + lane);
        uint2 u2 = __ldg(xp + (size_t)s2 * 32 + lane);
        uint2 u3 = __ldg(xp + (size_t)s3 * 32 + lane);
        acc4(acc, u0); acc4(acc, u1); acc4(acc, u2); acc4(acc, u3);
    }
    for (; i < end; ++i) {
        int s = __ldg(perm + i);
        acc4(acc, __ldg(xp + (size_t)s * 32 + lane));
    }
    float inv = 1.0f / (float)max(end - beg, 1);
    __half2 o0 = __floats2half2_rn(acc.x * inv, acc.y * inv);
    __half2 o1 = __floats2half2_rn(acc.z * inv, acc.w * inv);
    uint2 w; w.x = *(uint32_t*)&o0; w.y = *(uint32_t*)&o1;
    ((uint2*)agg)[(size_t)node * 32 + lane] = w;
}

// ---------------------------------------------------------------------------
// fp16 HMMA half-layer GEMM (K=128):
//   MODE 0: out = A @ W^T                         (store fp16, no epilogue)
//   MODE 1: out = relu( A @ W^T + bias + tmp )    (SAGE layer combine)
// Block 128x128, 8 warps (4x2), warp tile 32x64, mma m16n8k16.
// Proven R8 staging/fragment layout (AS_W=20, BS_W=68; conflict-free).
// ---------------------------------------------------------------------------
#define AS_W 20
#define BS_W 68

__device__ __forceinline__ void mma16(float* c, const uint32_t* a,
                                      uint32_t b0, uint32_t b1) {
    asm volatile(
        "mma.sync.aligned.m16n8k16.row.col.f32.f16.f16.f32 "
        "{%0,%1,%2,%3},{%4,%5,%6,%7},{%8,%9},{%0,%1,%2,%3};"
        : "+f"(c[0]), "+f"(c[1]), "+f"(c[2]), "+f"(c[3])
        : "r"(a[0]), "r"(a[1]), "r"(a[2]), "r"(a[3]), "r"(b0), "r"(b1));
}

template<int MODE>
__global__ void __launch_bounds__(256, 2)
k_gemm_f16(const __half* __restrict__ A,
           const float*  __restrict__ W,
           const __half* __restrict__ tmp,    // MODE 1 only
           const float*  __restrict__ bias,   // MODE 1 only
           __half* __restrict__ out, int M) {
    __shared__ uint32_t As[128 * AS_W];   // 10240 B
    __shared__ uint32_t Bs[128 * BS_W];   // 34816 B

    const int t    = threadIdx.x;
    const int lane = t & 31;
    const int wid  = t >> 5;
    const int wm   = wid & 3;
    const int wn   = wid >> 2;
    const int g    = lane >> 2;
    const int q    = lane & 3;
    const int m0   = blockIdx.x * 128;

    float c[2][8][4];
    #pragma unroll
    for (int mt = 0; mt < 2; ++mt)
        #pragma unroll
        for (int nt = 0; nt < 8; ++nt)
            #pragma unroll
            for (int j = 0; j < 4; ++j) c[mt][nt][j] = 0.f;

    // ---- stage full W (128x128) -> fp16 smem ----
    {
        int n = t >> 1, part = t & 1;
        #pragma unroll
        for (int cc = 0; cc < 4; ++cc) {
            const float4* wp = (const float4*)(W + (size_t)n * D + part * 64 + cc * 16);
            float4 f0 = wp[0], f1 = wp[1], f2 = wp[2], f3 = wp[3];
            __half2 h0 = __floats2half2_rn(f0.x, f0.y), h1 = __floats2half2_rn(f0.z, f0.w);
            __half2 h2 = __floats2half2_rn(f1.x, f1.y), h3 = __floats2half2_rn(f1.z, f1.w);
            __half2 h4 = __floats2half2_rn(f2.x, f2.y), h5 = __floats2half2_rn(f2.z, f2.w);
            __half2 h6 = __floats2half2_rn(f3.x, f3.y), h7 = __floats2half2_rn(f3.z, f3.w);
            uint4 u0, u1;
            u0.x = *(uint32_t*)&h0; u0.y = *(uint32_t*)&h1;
            u0.z = *(uint32_t*)&h2; u0.w = *(uint32_t*)&h3;
            u1.x = *(uint32_t*)&h4; u1.y = *(uint32_t*)&h5;
            u1.z = *(uint32_t*)&h6; u1.w = *(uint32_t*)&h7;
            uint32_t* d = Bs + n * BS_W + part * 32 + cc * 8;
            *(uint4*)d       = u0;
            *(uint4*)(d + 4) = u1;
        }
    }
    for (int kc = 0; kc < D; kc += 32) {
        // ---- stage A chunk: 128 rows x 32 halfs (16 halfs / thread) ----
        {
            int row = t >> 1, part = t & 1;
            int rg  = m0 + row;
            uint4 v0 = make_uint4(0, 0, 0, 0), v1 = v0;
            if (rg < M) {
                const uint4* ap = (const uint4*)(A + (size_t)rg * D + kc + part * 16);
                v0 = ap[0];
                v1 = ap[1];
            }
            uint32_t* dp = As + row * AS_W + part * 8;
            *(uint4*)dp       = v0;
            *(uint4*)(dp + 4) = v1;
        }
        __syncthreads();
        const int kw = kc >> 1;
        #pragma unroll
        for (int k0 = 0; k0 < 2; ++k0) {
            uint32_t a[2][4];
            #pragma unroll
            for (int mt = 0; mt < 2; ++mt) {
                const uint32_t* r0 = As + (wm * 32 + mt * 16 + g)     * AS_W + k0 * 8 + q;
                const uint32_t* r1 = As + (wm * 32 + mt * 16 + g + 8) * AS_W + k0 * 8 + q;
                a[mt][0] = r0[0];
                a[mt][1] = r1[0];
                a[mt][2] = r0[4];
                a[mt][3] = r1[4];
            }
            #pragma unroll
            for (int nt = 0; nt < 8; ++nt) {
                const uint32_t* bp = Bs + (wn * 64 + nt * 8 + g) * BS_W + kw + k0 * 8 + q;
                uint32_t b0 = bp[0], b1 = bp[4];
                mma16(c[0][nt], a[0], b0, b1);
                mma16(c[1][nt], a[1], b0, b1);
            }
        }
        __syncthreads();
    }

    // ---- epilogue ----
    #pragma unroll
    for (int mt = 0; mt < 2; ++mt) {
        #pragma unroll
        for (int nt = 0; nt < 8; ++nt) {
            int row = m0 + wm * 32 + mt * 16 + g;
            int col = wn * 64 + nt * 8 + 2 * q;
            float v0 = c[mt][nt][0], v1 = c[mt][nt][1];
            float v2 = c[mt][nt][2], v3 = c[mt][nt][3];
            if (MODE == 1) {
                float b0 = __ldg(bias + col), b1 = __ldg(bias + col + 1);
                if (row < M) {
                    __half2 tv = *(const __half2*)(tmp + (size_t)row * D + col);
                    float2 tf = __half22float2(tv);
                    v0 += b0 + tf.x; v1 += b1 + tf.y;
                }
                if (row + 8 < M) {
                    __half2 tv = *(const __half2*)(tmp + (size_t)(row + 8) * D + col);
                    float2 tf = __half22float2(tv);
                    v2 += b0 + tf.x; v3 += b1 + tf.y;
                }
                v0 = fmaxf(v0, 0.f); v1 = fmaxf(v1, 0.f);
                v2 = fmaxf(v2, 0.f); v3 = fmaxf(v3, 0.f);
            }
            if (row < M) {
                __half2 h = __floats2half2_rn(v0, v1);
                *(__half2*)(out + (size_t)row * D + col) = h;
            }
            if (row + 8 < M) {
                __half2 h = __floats2half2_rn(v2, v3);
                *(__half2*)(out + (size_t)(row + 8) * D + col) = h;
            }
        }
    }
}

// ---------------------------------------------------------------------------
// Output layer: out[m, 0..3] = h[m,:] @ w_out^T + b_out.  One warp per row.
// ---------------------------------------------------------------------------
__global__ void k_out(const __half* __restrict__ h,
                      const float* __restrict__ w,
                      const float* __restrict__ b,
                      float* __restrict__ out, int M) {
    int gid  = blockIdx.x * blockDim.x + threadIdx.x;
    int row  = gid >> 5;
    int lane = gid & 31;
    if (row >= M) return;
    uint2 u = __ldg((const uint2*)h + (size_t)row * 32 + lane);
    __half2 h0 = *(__half2*)&u.x, h1 = *(__half2*)&u.y;
    float2 f0 = __half22float2(h0), f1 = __half22float2(h1);
    float r[4];
    #pragma unroll
    for (int o = 0; o < 4; ++o) {
        float4 wv = __ldg((const float4*)(w + o * D) + lane);
        float p = f0.x * wv.x + f0.y * wv.y + f1.x * wv.z + f1.y * wv.w;
        #pragma unroll
        for (int s = 16; s > 0; s >>= 1)
            p += __shfl_xor_sync(0xffffffffu, p, s);
        r[o] = p;
    }
    if (lane == 0) {
        *(float4*)(out + (size_t)row * 4) =
            make_float4(r[0] + b[0], r[1] + b[1], r[2] + b[2], r[3] + b[3]);
    }
}

// ---------------------------------------------------------------------------
extern "C" void kernel_launch(void* const* d_in, const int* in_sizes, int n_in,
                              void* d_out, int out_size) {
    const float* x     = (const float*)d_in[0];
    const int*   ei    = (const int*)  d_in[1];
    const float* w1_l  = (const float*)d_in[2];
    const float* b1_l  = (const float*)d_in[3];
    const float* w1_r  = (const float*)d_in[4];
    const float* w2_l  = (const float*)d_in[5];
    const float* b2_l  = (const float*)d_in[6];
    const float* w2_r  = (const float*)d_in[7];
    const float* w_out = (const float*)d_in[8];
    const float* b_out = (const float*)d_in[9];
    float*       out   = (float*)d_out;

    const int E    = in_sizes[1] / 2;
    const int* src = ei;
    const int* dst = ei + E;

    __half *xh, *agg, *h1, *h2, *tmp;
    int *cnt, *rowstart, *cursor, *perm;
    cudaGetSymbolAddress((void**)&xh,       g_xh);
    cudaGetSymbolAddress((void**)&agg,      g_agg);
    cudaGetSymbolAddress((void**)&h1,       g_h1);
    cudaGetSymbolAddress((void**)&h2,       g_h2);
    cudaGetSymbolAddress((void**)&tmp,      g_tmp);
    cudaGetSymbolAddress((void**)&cnt,      g_cnt);
    cudaGetSymbolAddress((void**)&rowstart, g_rowstart);
    cudaGetSymbolAddress((void**)&cursor,   g_cursor);
    cudaGetSymbolAddress((void**)&perm,     g_perm);

    const int M      = N_NODES;
    const int n8     = M * D / 8;
    const int prep_n = (E > n8) ? E : n8;
    const int prep_b = (prep_n + 255) / 256;
    const int eb     = (E + 255) / 256;
    const int gath_b = (M + 7) / 8;
    const int gemm_b = (M + 127) / 128;
    const int out_b  = (M * 32 + 255) / 256;

    // ---- setup ----
    k_prep   <<<prep_b, 256>>>(x, dst, xh, cnt, E, n8);
    k_scan   <<<1, 1024>>>(cnt, rowstart, cursor, E);
    k_permute<<<eb, 256>>>(src, dst, cursor, perm, E);

    // ---- Layer 1 ----
    // launch index 3 (PROFILED): pure fp16 HMMA GEMM, x @ w1_r^T -> tmp
    k_gemm_f16<0><<<gemm_b, 256>>>(xh, w1_r, nullptr, nullptr, tmp, M);
    k_gather  <<<gath_b, 256>>>(xh, perm, rowstart, agg);
    k_gemm_f16<1><<<gemm_b, 256>>>(agg, w1_l, tmp, b1_l, h1, M);

    // ---- Layer 2 ----
    k_gemm_f16<0><<<gemm_b, 256>>>(h1, w2_r, nullptr, nullptr, tmp, M);
    k_gather  <<<gath_b, 256>>>(h1, perm, rowstart, agg);
    k_gemm_f16<1><<<gemm_b, 256>>>(agg, w2_l, tmp, b2_l, h2, M);

    // ---- Output projection ----
    k_out<<<out_b, 256>>>(h2, w_out, b_out, out, M);
}

// round 11
// speedup vs baseline: 1.1345x; 1.1345x over previous
#include <cuda_runtime.h>
#include <cuda_fp16.h>
#include <cstdint>

#define N_NODES 100000
#define D 128
#define MAXE 2000000

// ---------------- device scratch (no allocations allowed) -------------------
__device__ __half g_xh [N_NODES * D];     // fp16 copy of x
__device__ __half g_agg[N_NODES * D];     // aggregated means (fp16)
__device__ __half g_h1 [N_NODES * D];     // layer-1 activations (fp16)
__device__ __half g_h2 [N_NODES * D];     // layer-2 activations (fp16)
__device__ int    g_cnt[N_NODES];         // degree histogram (re-zeroed by scan)
__device__ int    g_rowstart[N_NODES + 1];
__device__ int    g_cursor[N_NODES];
__device__ int    g_perm[MAXE];           // dst-sorted src indices

// ---------------------------------------------------------------------------
// prep: convert x -> fp16 AND histogram dst degrees (fused, one launch)
// ---------------------------------------------------------------------------
__global__ void k_prep(const float* __restrict__ x, const int* __restrict__ dst,
                       __half* __restrict__ xh, int* __restrict__ cnt,
                       int E, int n8) {
    int i = blockIdx.x * blockDim.x + threadIdx.x;
    if (i < n8) {
        const float4* xp = (const float4*)x + (size_t)i * 2;
        float4 v0 = xp[0], v1 = xp[1];
        __half2 p0 = __floats2half2_rn(v0.x, v0.y);
        __half2 p1 = __floats2half2_rn(v0.z, v0.w);
        __half2 p2 = __floats2half2_rn(v1.x, v1.y);
        __half2 p3 = __floats2half2_rn(v1.z, v1.w);
        uint4 w;
        w.x = *(uint32_t*)&p0; w.y = *(uint32_t*)&p1;
        w.z = *(uint32_t*)&p2; w.w = *(uint32_t*)&p3;
        ((uint4*)xh)[i] = w;
    }
    if (i < E) atomicAdd(cnt + __ldg(dst + i), 1);
}

// ---------------------------------------------------------------------------
// Coalesced single-block scan (warp-shuffle); re-zeroes cnt for graph replay.
// ---------------------------------------------------------------------------
__global__ void __launch_bounds__(1024) k_scan(int* __restrict__ cnt,
                                               int* __restrict__ rowstart,
                                               int* __restrict__ cursor, int E) {
    __shared__ int wsum[32];
    const int t    = threadIdx.x;
    const int lane = t & 31;
    const int wid  = t >> 5;
    int carry = 0;
    for (int base = 0; base < N_NODES; base += 1024) {
        int i = base + t;
        int v = (i < N_NODES) ? cnt[i] : 0;
        int s = v;
        #pragma unroll
        for (int off = 1; off < 32; off <<= 1) {
            int u = __shfl_up_sync(0xffffffffu, s, off);
            if (lane >= off) s += u;
        }
        if (lane == 31) wsum[wid] = s;
        __syncthreads();
        if (wid == 0) {
            int w = wsum[lane];
            #pragma unroll
            for (int off = 1; off < 32; off <<= 1) {
                int u = __shfl_up_sync(0xffffffffu, w, off);
                if (lane >= off) w += u;
            }
            wsum[lane] = w;
        }
        __syncthreads();
        int wofs = (wid > 0) ? wsum[wid - 1] : 0;
        int excl = carry + wofs + (s - v);
        if (i < N_NODES) {
            rowstart[i] = excl;
            cursor[i]   = excl;
            cnt[i]      = 0;
        }
        int tot = wsum[31];
        __syncthreads();
        carry += tot;
    }
    if (t == 0) rowstart[N_NODES] = E;
}

// ---------------------------------------------------------------------------
__global__ void k_permute(const int* __restrict__ src, const int* __restrict__ dst,
                          int* __restrict__ cursor, int* __restrict__ perm, int E) {
    int e = blockIdx.x * blockDim.x + threadIdx.x;
    if (e < E) {
        int pos = atomicAdd(cursor + __ldg(dst + e), 1);
        perm[pos] = __ldg(src + e);
    }
}

// ---------------------------------------------------------------------------
// CSR gather-mean over fp16 rows (measured 41.5us)
// ---------------------------------------------------------------------------
__device__ __forceinline__ void acc4(float4& a, uint2 u) {
    __half2 h0 = *(__half2*)&u.x, h1 = *(__half2*)&u.y;
    float2 f0 = __half22float2(h0), f1 = __half22float2(h1);
    a.x += f0.x; a.y += f0.y; a.z += f1.x; a.w += f1.y;
}

__global__ void __launch_bounds__(256)
k_gather(const __half* __restrict__ xh, const int* __restrict__ perm,
         const int* __restrict__ rowstart, __half* __restrict__ agg) {
    int node = blockIdx.x * 8 + (threadIdx.x >> 5);
    int lane = threadIdx.x & 31;
    if (node >= N_NODES) return;
    int beg = __ldg(rowstart + node);
    int end = __ldg(rowstart + node + 1);
    const uint2* xp = (const uint2*)xh;
    float4 acc = make_float4(0.f, 0.f, 0.f, 0.f);
    int i = beg;
    for (; i + 4 <= end; i += 4) {
        int s0 = __ldg(perm + i),     s1 = __ldg(perm + i + 1);
        int s2 = __ldg(perm + i + 2), s3 = __ldg(perm + i + 3);
        uint2 u0 = __ldg(xp + (size_t)s0 * 32 + lane);
        uint2 u1 = __ldg(xp + (size_t)s1 * 32 + lane);
        uint2 u2 = __ldg(xp + (size_t)s2 * 32 + lane);
        uint2 u3 = __ldg(xp + (size_t)s3 * 32 + lane);
        acc4(acc, u0); acc4(acc, u1); acc4(acc, u2); acc4(acc, u3);
    }
    for (; i < end; ++i) {
        int s = __ldg(perm + i);
        acc4(acc, __ldg(xp + (size_t)s * 32 + lane));
    }
    float inv = 1.0f / (float)max(end - beg, 1);
    __half2 o0 = __floats2half2_rn(acc.x * inv, acc.y * inv);
    __half2 o1 = __floats2half2_rn(acc.z * inv, acc.w * inv);
    uint2 w; w.x = *(uint32_t*)&o0; w.y = *(uint32_t*)&o1;
    ((uint2*)agg)[(size_t)node * 32 + lane] = w;
}

// ---------------------------------------------------------------------------
// fp16 HMMA SAGE GEMM with ldmatrix fragment loads:
//   out = relu( agg @ Wl^T + bias + A2 @ Wr^T ), fp16 out
// Block 128x128, 8 warps (4x2), warp tile 32x64, mma m16n8k16.
// Smem: As[row][kword] stride 20, Bs[n][kword] stride 68 (full W per phase).
// Fragments via ldmatrix.m8n8.x4: 12 LDSM per 32-k chunk vs 48 LDS.32 before.
// ---------------------------------------------------------------------------
#define AS_W 20
#define BS_W 68

__device__ __forceinline__ uint32_t smem_u32(const void* p) {
    return (uint32_t)__cvta_generic_to_shared(p);
}

__device__ __forceinline__ void mma16(float* c, const uint32_t* a,
                                      uint32_t b0, uint32_t b1) {
    asm volatile(
        "mma.sync.aligned.m16n8k16.row.col.f32.f16.f16.f32 "
        "{%0,%1,%2,%3},{%4,%5,%6,%7},{%8,%9},{%0,%1,%2,%3};"
        : "+f"(c[0]), "+f"(c[1]), "+f"(c[2]), "+f"(c[3])
        : "r"(a[0]), "r"(a[1]), "r"(a[2]), "r"(a[3]), "r"(b0), "r"(b1));
}

__device__ __forceinline__ void ldsm4(uint32_t& r0, uint32_t& r1,
                                      uint32_t& r2, uint32_t& r3, uint32_t addr) {
    asm volatile("ldmatrix.sync.aligned.m8n8.x4.shared.b16 {%0,%1,%2,%3}, [%4];"
                 : "=r"(r0), "=r"(r1), "=r"(r2), "=r"(r3) : "r"(addr));
}

__global__ void __launch_bounds__(256, 2)
k_gemm(const __half* __restrict__ A1,   // agg
       const __half* __restrict__ A2,   // x or h1 (fp16)
       const float* __restrict__ Wl,
       const float* __restrict__ bias,
       const float* __restrict__ Wr,
       __half* __restrict__ out, int M) {
    __shared__ uint32_t As[128 * AS_W];   // 10240 B
    __shared__ uint32_t Bs[128 * BS_W];   // 34816 B

    const int t    = threadIdx.x;
    const int lane = t & 31;
    const int wid  = t >> 5;
    const int wm   = wid & 3;
    const int wn   = wid >> 2;
    const int g    = lane >> 2;
    const int q    = lane & 3;
    const int m0   = blockIdx.x * 128;

    // ldmatrix lane-address components (word units)
    // A x4: m0 rows0-7/k0-7, m1 rows8-15/k0-7, m2 rows0-7/k8-15, m3 rows8-15/k8-15
    const uint32_t a_lane = (uint32_t)(((lane & 7) + ((lane >> 3) & 1) * 8) * AS_W
                                       + (lane >> 4) * 4);
    // B x4: m0 n0-7/k0-7, m1 n0-7/k8-15, m2 n8-15/k0-7, m3 n8-15/k8-15
    const uint32_t b_lane = (uint32_t)(((lane & 7) + (lane >> 4) * 8) * BS_W
                                       + ((lane >> 3) & 1) * 4);
    const uint32_t a_base = smem_u32(As);
    const uint32_t b_base = smem_u32(Bs);

    float c[2][8][4];
    #pragma unroll
    for (int mt = 0; mt < 2; ++mt)
        #pragma unroll
        for (int nt = 0; nt < 8; ++nt)
            #pragma unroll
            for (int j = 0; j < 4; ++j) c[mt][nt][j] = 0.f;

    #pragma unroll
    for (int p = 0; p < 2; ++p) {
        const __half* A = p ? A2 : A1;
        const float*  W = p ? Wr : Wl;

        // ---- stage full W (128x128) -> fp16 smem, once per phase ----
        {
            int n = t >> 1, part = t & 1;
            #pragma unroll
            for (int cc = 0; cc < 4; ++cc) {
                const float4* wp = (const float4*)(W + (size_t)n * D + part * 64 + cc * 16);
                float4 f0 = wp[0], f1 = wp[1], f2 = wp[2], f3 = wp[3];
                __half2 h0 = __floats2half2_rn(f0.x, f0.y), h1 = __floats2half2_rn(f0.z, f0.w);
                __half2 h2 = __floats2half2_rn(f1.x, f1.y), h3 = __floats2half2_rn(f1.z, f1.w);
                __half2 h4 = __floats2half2_rn(f2.x, f2.y), h5 = __floats2half2_rn(f2.z, f2.w);
                __half2 h6 = __floats2half2_rn(f3.x, f3.y), h7 = __floats2half2_rn(f3.z, f3.w);
                uint4 u0, u1;
                u0.x = *(uint32_t*)&h0; u0.y = *(uint32_t*)&h1;
                u0.z = *(uint32_t*)&h2; u0.w = *(uint32_t*)&h3;
                u1.x = *(uint32_t*)&h4; u1.y = *(uint32_t*)&h5;
                u1.z = *(uint32_t*)&h6; u1.w = *(uint32_t*)&h7;
                uint32_t* d = Bs + n * BS_W + part * 32 + cc * 8;
                *(uint4*)d       = u0;
                *(uint4*)(d + 4) = u1;
            }
        }
        for (int kc = 0; kc < D; kc += 32) {
            // ---- stage A chunk: 128 rows x 32 halfs (16 halfs / thread) ----
            {
                int row = t >> 1, part = t & 1;
                int rg  = m0 + row;
                uint4 v0 = make_uint4(0, 0, 0, 0), v1 = v0;
                if (rg < M) {
                    const uint4* ap = (const uint4*)(A + (size_t)rg * D + kc + part * 16);
                    v0 = ap[0];
                    v1 = ap[1];
                }
                uint32_t* dp = As + row * AS_W + part * 8;
                *(uint4*)dp       = v0;
                *(uint4*)(dp + 4) = v1;
            }
            __syncthreads();
            const uint32_t kw = (uint32_t)(kc >> 1);
            #pragma unroll
            for (int k0 = 0; k0 < 2; ++k0) {
                uint32_t a[2][4];
                #pragma unroll
                for (int mt = 0; mt < 2; ++mt) {
                    uint32_t addr = a_base +
                        ((uint32_t)((wm * 32 + mt * 16) * AS_W) + k0 * 8 + a_lane) * 4;
                    ldsm4(a[mt][0], a[mt][1], a[mt][2], a[mt][3], addr);
                }
                #pragma unroll
                for (int np = 0; np < 4; ++np) {
                    uint32_t addr = b_base +
                        ((uint32_t)((wn * 64 + np * 16) * BS_W) + kw + k0 * 8 + b_lane) * 4;
                    uint32_t b[4];
                    ldsm4(b[0], b[1], b[2], b[3], addr);
                    mma16(c[0][2 * np],     a[0], b[0], b[1]);
                    mma16(c[1][2 * np],     a[1], b[0], b[1]);
                    mma16(c[0][2 * np + 1], a[0], b[2], b[3]);
                    mma16(c[1][2 * np + 1], a[1], b[2], b[3]);
                }
            }
            __syncthreads();
        }
    }

    // ---- epilogue: bias + relu + fp16 store ----
    #pragma unroll
    for (int mt = 0; mt < 2; ++mt) {
        #pragma unroll
        for (int nt = 0; nt < 8; ++nt) {
            int row = m0 + wm * 32 + mt * 16 + g;
            int col = wn * 64 + nt * 8 + 2 * q;
            float b0 = __ldg(bias + col), b1 = __ldg(bias + col + 1);
            float v0 = fmaxf(c[mt][nt][0] + b0, 0.f);
            float v1 = fmaxf(c[mt][nt][1] + b1, 0.f);
            float v2 = fmaxf(c[mt][nt][2] + b0, 0.f);
            float v3 = fmaxf(c[mt][nt][3] + b1, 0.f);
            if (row < M) {
                __half2 h = __floats2half2_rn(v0, v1);
                *(__half2*)(out + (size_t)row * D + col) = h;
            }
            if (row + 8 < M) {
                __half2 h = __floats2half2_rn(v2, v3);
                *(__half2*)(out + (size_t)(row + 8) * D + col) = h;
            }
        }
    }
}

// ---------------------------------------------------------------------------
// Output layer: out[m, 0..3] = h[m,:] @ w_out^T + b_out.  One warp per row.
// ---------------------------------------------------------------------------
__global__ void k_out(const __half* __restrict__ h,
                      const float* __restrict__ w,
                      const float* __restrict__ b,
                      float* __restrict__ out, int M) {
    int gid  = blockIdx.x * blockDim.x + threadIdx.x;
    int row  = gid >> 5;
    int lane = gid & 31;
    if (row >= M) return;
    uint2 u = __ldg((const uint2*)h + (size_t)row * 32 + lane);
    __half2 h0 = *(__half2*)&u.x, h1 = *(__half2*)&u.y;
    float2 f0 = __half22float2(h0), f1 = __half22float2(h1);
    float r[4];
    #pragma unroll
    for (int o = 0; o < 4; ++o) {
        float4 wv = __ldg((const float4*)(w + o * D) + lane);
        float p = f0.x * wv.x + f0.y * wv.y + f1.x * wv.z + f1.y * wv.w;
        #pragma unroll
        for (int s = 16; s > 0; s >>= 1)
            p += __shfl_xor_sync(0xffffffffu, p, s);
        r[o] = p;
    }
    if (lane == 0) {
        *(float4*)(out + (size_t)row * 4) =
            make_float4(r[0] + b[0], r[1] + b[1], r[2] + b[2], r[3] + b[3]);
    }
}

// ---------------------------------------------------------------------------
extern "C" void kernel_launch(void* const* d_in, const int* in_sizes, int n_in,
                              void* d_out, int out_size) {
    const float* x     = (const float*)d_in[0];
    const int*   ei    = (const int*)  d_in[1];
    const float* w1_l  = (const float*)d_in[2];
    const float* b1_l  = (const float*)d_in[3];
    const float* w1_r  = (const float*)d_in[4];
    const float* w2_l  = (const float*)d_in[5];
    const float* b2_l  = (const float*)d_in[6];
    const float* w2_r  = (const float*)d_in[7];
    const float* w_out = (const float*)d_in[8];
    const float* b_out = (const float*)d_in[9];
    float*       out   = (float*)d_out;

    const int E    = in_sizes[1] / 2;
    const int* src = ei;
    const int* dst = ei + E;

    __half *xh, *agg, *h1, *h2;
    int *cnt, *rowstart, *cursor, *perm;
    cudaGetSymbolAddress((void**)&xh,       g_xh);
    cudaGetSymbolAddress((void**)&agg,      g_agg);
    cudaGetSymbolAddress((void**)&h1,       g_h1);
    cudaGetSymbolAddress((void**)&h2,       g_h2);
    cudaGetSymbolAddress((void**)&cnt,      g_cnt);
    cudaGetSymbolAddress((void**)&rowstart, g_rowstart);
    cudaGetSymbolAddress((void**)&cursor,   g_cursor);
    cudaGetSymbolAddress((void**)&perm,     g_perm);

    const int M      = N_NODES;
    const int n8     = M * D / 8;
    const int prep_n = (E > n8) ? E : n8;
    const int prep_b = (prep_n + 255) / 256;
    const int eb     = (E + 255) / 256;
    const int gath_b = (M + 7) / 8;
    const int gemm_b = (M + 127) / 128;
    const int out_b  = (M * 32 + 255) / 256;

    // ---- setup ----
    k_prep   <<<prep_b, 256>>>(x, dst, xh, cnt, E, n8);
    k_scan   <<<1, 1024>>>(cnt, rowstart, cursor, E);
    k_permute<<<eb, 256>>>(src, dst, cursor, perm, E);

    // ---- Layer 1 ----
    k_gather<<<gath_b, 256>>>(xh, perm, rowstart, agg);
    k_gemm  <<<gemm_b, 256>>>(agg, xh, w1_l, b1_l, w1_r, h1, M);

    // ---- Layer 2 ----
    k_gather<<<gath_b, 256>>>(h1, perm, rowstart, agg);
    k_gemm  <<<gemm_b, 256>>>(agg, h1, w2_l, b2_l, w2_r, h2, M);

    // ---- Output projection ----
    k_out<<<out_b, 256>>>(h2, w_out, b_out, out, M);
}

// round 12
// speedup vs baseline: 1.3275x; 1.1701x over previous
#include <cuda_runtime.h>
#include <cuda_fp16.h>
#include <cstdint>

#define N_NODES 100000
#define D 128
#define MAXE 2000000

// ---------------- device scratch (no allocations allowed) -------------------
__device__ __half g_xh [N_NODES * D];     // fp16 copy of x
__device__ __half g_agg[N_NODES * D];     // aggregated means (fp16)
__device__ __half g_h1 [N_NODES * D];     // layer-1 activations (fp16)
__device__ __half g_h2 [N_NODES * D];     // layer-2 activations (fp16)
__device__ __half g_wh [4 * D * D];       // fp16 weights: w1_l, w1_r, w2_l, w2_r
__device__ int    g_cnt[N_NODES];         // degree histogram (re-zeroed by scan)
__device__ int    g_rowstart[N_NODES + 1];
__device__ int    g_cursor[N_NODES];
__device__ int    g_perm[MAXE];           // dst-sorted src indices

// ---------------------------------------------------------------------------
// prep: convert x AND all 4 weight matrices -> fp16, histogram dst degrees
// ---------------------------------------------------------------------------
__device__ __forceinline__ uint4 cvt8(const float4* src) {
    float4 v0 = src[0], v1 = src[1];
    __half2 p0 = __floats2half2_rn(v0.x, v0.y);
    __half2 p1 = __floats2half2_rn(v0.z, v0.w);
    __half2 p2 = __floats2half2_rn(v1.x, v1.y);
    __half2 p3 = __floats2half2_rn(v1.z, v1.w);
    uint4 w;
    w.x = *(uint32_t*)&p0; w.y = *(uint32_t*)&p1;
    w.z = *(uint32_t*)&p2; w.w = *(uint32_t*)&p3;
    return w;
}

__global__ void k_prep(const float* __restrict__ x, const int* __restrict__ dst,
                       const float* __restrict__ w1l, const float* __restrict__ w1r,
                       const float* __restrict__ w2l, const float* __restrict__ w2r,
                       __half* __restrict__ xh, __half* __restrict__ wh,
                       int* __restrict__ cnt, int E, int n8) {
    int i = blockIdx.x * blockDim.x + threadIdx.x;
    if (i < n8) {
        ((uint4*)xh)[i] = cvt8((const float4*)x + (size_t)i * 2);
    } else if (i < n8 + 8192) {            // 4 weights x 2048 uint4 units
        int j = i - n8;
        int which = j >> 11, off = j & 2047;
        const float* W = (which == 0) ? w1l : (which == 1) ? w1r
                       : (which == 2) ? w2l : w2r;
        ((uint4*)wh)[j] = cvt8((const float4*)(W + off * 8));
    }
    if (i < E) atomicAdd(cnt + __ldg(dst + i), 1);
}

// ---------------------------------------------------------------------------
// Coalesced single-block scan (warp-shuffle); re-zeroes cnt for graph replay.
// ---------------------------------------------------------------------------
__global__ void __launch_bounds__(1024) k_scan(int* __restrict__ cnt,
                                               int* __restrict__ rowstart,
                                               int* __restrict__ cursor, int E) {
    __shared__ int wsum[32];
    const int t    = threadIdx.x;
    const int lane = t & 31;
    const int wid  = t >> 5;
    int carry = 0;
    for (int base = 0; base < N_NODES; base += 1024) {
        int i = base + t;
        int v = (i < N_NODES) ? cnt[i] : 0;
        int s = v;
        #pragma unroll
        for (int off = 1; off < 32; off <<= 1) {
            int u = __shfl_up_sync(0xffffffffu, s, off);
            if (lane >= off) s += u;
        }
        if (lane == 31) wsum[wid] = s;
        __syncthreads();
        if (wid == 0) {
            int w = wsum[lane];
            #pragma unroll
            for (int off = 1; off < 32; off <<= 1) {
                int u = __shfl_up_sync(0xffffffffu, w, off);
                if (lane >= off) w += u;
            }
            wsum[lane] = w;
        }
        __syncthreads();
        int wofs = (wid > 0) ? wsum[wid - 1] : 0;
        int excl = carry + wofs + (s - v);
        if (i < N_NODES) {
            rowstart[i] = excl;
            cursor[i]   = excl;
            cnt[i]      = 0;
        }
        int tot = wsum[31];
        __syncthreads();
        carry += tot;
    }
    if (t == 0) rowstart[N_NODES] = E;
}

// ---------------------------------------------------------------------------
__global__ void k_permute(const int* __restrict__ src, const int* __restrict__ dst,
                          int* __restrict__ cursor, int* __restrict__ perm, int E) {
    int e = blockIdx.x * blockDim.x + threadIdx.x;
    if (e < E) {
        int pos = atomicAdd(cursor + __ldg(dst + e), 1);
        perm[pos] = __ldg(src + e);
    }
}

// ---------------------------------------------------------------------------
// CSR gather-mean over fp16 rows (measured 41.4us)
// ---------------------------------------------------------------------------
__device__ __forceinline__ void acc4(float4& a, uint2 u) {
    __half2 h0 = *(__half2*)&u.x, h1 = *(__half2*)&u.y;
    float2 f0 = __half22float2(h0), f1 = __half22float2(h1);
    a.x += f0.x; a.y += f0.y; a.z += f1.x; a.w += f1.y;
}

__global__ void __launch_bounds__(256)
k_gather(const __half* __restrict__ xh, const int* __restrict__ perm,
         const int* __restrict__ rowstart, __half* __restrict__ agg) {
    int node = blockIdx.x * 8 + (threadIdx.x >> 5);
    int lane = threadIdx.x & 31;
    if (node >= N_NODES) return;
    int beg = __ldg(rowstart + node);
    int end = __ldg(rowstart + node + 1);
    const uint2* xp = (const uint2*)xh;
    float4 acc = make_float4(0.f, 0.f, 0.f, 0.f);
    int i = beg;
    for (; i + 4 <= end; i += 4) {
        int s0 = __ldg(perm + i),     s1 = __ldg(perm + i + 1);
        int s2 = __ldg(perm + i + 2), s3 = __ldg(perm + i + 3);
        uint2 u0 = __ldg(xp + (size_t)s0 * 32 + lane);
        uint2 u1 = __ldg(xp + (size_t)s1 * 32 + lane);
        uint2 u2 = __ldg(xp + (size_t)s2 * 32 + lane);
        uint2 u3 = __ldg(xp + (size_t)s3 * 32 + lane);
        acc4(acc, u0); acc4(acc, u1); acc4(acc, u2); acc4(acc, u3);
    }
    for (; i < end; ++i) {
        int s = __ldg(perm + i);
        acc4(acc, __ldg(xp + (size_t)s * 32 + lane));
    }
    float inv = 1.0f / (float)max(end - beg, 1);
    __half2 o0 = __floats2half2_rn(acc.x * inv, acc.y * inv);
    __half2 o1 = __floats2half2_rn(acc.z * inv, acc.w * inv);
    uint2 w; w.x = *(uint32_t*)&o0; w.y = *(uint32_t*)&o1;
    ((uint2*)agg)[(size_t)node * 32 + lane] = w;
}

// ---------------------------------------------------------------------------
// fp16 HMMA SAGE GEMM, cp.async double-buffered:
//   out = relu( agg @ Wl^T + bias + A2 @ Wr^T ), fp16 out
// Unified K=256 loop: 8 chunks of 32k; chunks 0-3 use (agg, Wl), 4-7 (A2, Wr).
// Per chunk: A tile 128x32h + B tile 128x32h staged via cp.async.cg (ping/pong),
// prefetch of chunk c+1 overlaps MMA of chunk c. Frags via ldmatrix (stride 20).
// ---------------------------------------------------------------------------
#define TS_W 20

__device__ __forceinline__ uint32_t smem_u32(const void* p) {
    return (uint32_t)__cvta_generic_to_shared(p);
}

__device__ __forceinline__ void cpa16(uint32_t dst, const void* src, int sz) {
    asm volatile("cp.async.cg.shared.global [%0], [%1], 16, %2;"
                 :: "r"(dst), "l"(src), "r"(sz));
}
#define CPA_COMMIT() asm volatile("cp.async.commit_group;" ::: "memory")
#define CPA_WAIT1()  asm volatile("cp.async.wait_group 1;" ::: "memory")
#define CPA_WAIT0()  asm volatile("cp.async.wait_group 0;" ::: "memory")

__device__ __forceinline__ void mma16(float* c, const uint32_t* a,
                                      uint32_t b0, uint32_t b1) {
    asm volatile(
        "mma.sync.aligned.m16n8k16.row.col.f32.f16.f16.f32 "
        "{%0,%1,%2,%3},{%4,%5,%6,%7},{%8,%9},{%0,%1,%2,%3};"
        : "+f"(c[0]), "+f"(c[1]), "+f"(c[2]), "+f"(c[3])
        : "r"(a[0]), "r"(a[1]), "r"(a[2]), "r"(a[3]), "r"(b0), "r"(b1));
}

__device__ __forceinline__ void ldsm4(uint32_t& r0, uint32_t& r1,
                                      uint32_t& r2, uint32_t& r3, uint32_t addr) {
    asm volatile("ldmatrix.sync.aligned.m8n8.x4.shared.b16 {%0,%1,%2,%3}, [%4];"
                 : "=r"(r0), "=r"(r1), "=r"(r2), "=r"(r3) : "r"(addr));
}

__global__ void __launch_bounds__(256, 2)
k_gemm(const __half* __restrict__ A1,   // agg
       const __half* __restrict__ A2,   // x or h1 (fp16)
       const __half* __restrict__ Wl,   // fp16 weights
       const __half* __restrict__ Wr,
       const float* __restrict__ bias,
       __half* __restrict__ out, int M) {
    __shared__ uint32_t As[2][128 * TS_W];   // 2 x 10240 B
    __shared__ uint32_t Bs[2][128 * TS_W];   // 2 x 10240 B   (40960 B total)

    const int t    = threadIdx.x;
    const int lane = t & 31;
    const int wid  = t >> 5;
    const int wm   = wid & 3;
    const int wn   = wid >> 2;
    const int g    = lane >> 2;
    const int q    = lane & 3;
    const int m0   = blockIdx.x * 128;

    const int srow = t >> 1;          // staging row 0..127
    const int part = t & 1;           // 0/1 halves of 32-half row chunk
    const int rgA  = m0 + srow;
    const int szA  = (rgA < M) ? 16 : 0;

    const uint32_t a_lane = (uint32_t)(((lane & 7) + ((lane >> 3) & 1) * 8) * TS_W
                                       + (lane >> 4) * 4);
    const uint32_t b_lane = (uint32_t)(((lane & 7) + (lane >> 4) * 8) * TS_W
                                       + ((lane >> 3) & 1) * 4);
    const uint32_t a_base0 = smem_u32(&As[0][0]);
    const uint32_t a_base1 = smem_u32(&As[1][0]);
    const uint32_t b_base0 = smem_u32(&Bs[0][0]);
    const uint32_t b_base1 = smem_u32(&Bs[1][0]);
    const uint32_t st_off  = (uint32_t)(srow * TS_W + part * 8) * 4;

    float c[2][8][4];
    #pragma unroll
    for (int mt = 0; mt < 2; ++mt)
        #pragma unroll
        for (int nt = 0; nt < 8; ++nt)
            #pragma unroll
            for (int j = 0; j < 4; ++j) c[mt][nt][j] = 0.f;

    // stage chunk cc into buffer bb
    auto stage = [&](int cc, int bb) {
        const __half* A = (cc < 4) ? A1 : A2;
        const __half* W = (cc < 4) ? Wl : Wr;
        int kc = (cc & 3) * 32;
        uint32_t ab = bb ? a_base1 : a_base0;
        uint32_t bbb = bb ? b_base1 : b_base0;
        const __half* as = A + (size_t)rgA * D + kc + part * 16;
        const __half* ws = W + (size_t)srow * D + kc + part * 16;
        cpa16(ab + st_off,      as,     szA);
        cpa16(ab + st_off + 16, as + 8, szA);
        cpa16(bbb + st_off,      ws,     16);
        cpa16(bbb + st_off + 16, ws + 8, 16);
    };

    stage(0, 0);
    CPA_COMMIT();

    for (int cc = 0; cc < 8; ++cc) {
        if (cc < 7) {
            stage(cc + 1, (cc + 1) & 1);
            CPA_COMMIT();
            CPA_WAIT1();
        } else {
            CPA_WAIT0();
        }
        __syncthreads();

        const uint32_t ab = (cc & 1) ? a_base1 : a_base0;
        const uint32_t bb = (cc & 1) ? b_base1 : b_base0;
        #pragma unroll
        for (int k0 = 0; k0 < 2; ++k0) {
            uint32_t a[2][4];
            #pragma unroll
            for (int mt = 0; mt < 2; ++mt) {
                uint32_t addr = ab +
                    ((uint32_t)((wm * 32 + mt * 16) * TS_W) + k0 * 8 + a_lane) * 4;
                ldsm4(a[mt][0], a[mt][1], a[mt][2], a[mt][3], addr);
            }
            #pragma unroll
            for (int np = 0; np < 4; ++np) {
                uint32_t addr = bb +
                    ((uint32_t)((wn * 64 + np * 16) * TS_W) + k0 * 8 + b_lane) * 4;
                uint32_t b[4];
                ldsm4(b[0], b[1], b[2], b[3], addr);
                mma16(c[0][2 * np],     a[0], b[0], b[1]);
                mma16(c[1][2 * np],     a[1], b[0], b[1]);
                mma16(c[0][2 * np + 1], a[0], b[2], b[3]);
                mma16(c[1][2 * np + 1], a[1], b[2], b[3]);
            }
        }
        __syncthreads();
    }

    // ---- epilogue: bias + relu + fp16 store ----
    #pragma unroll
    for (int mt = 0; mt < 2; ++mt) {
        #pragma unroll
        for (int nt = 0; nt < 8; ++nt) {
            int row = m0 + wm * 32 + mt * 16 + g;
            int col = wn * 64 + nt * 8 + 2 * q;
            float b0 = __ldg(bias + col), b1 = __ldg(bias + col + 1);
            float v0 = fmaxf(c[mt][nt][0] + b0, 0.f);
            float v1 = fmaxf(c[mt][nt][1] + b1, 0.f);
            float v2 = fmaxf(c[mt][nt][2] + b0, 0.f);
            float v3 = fmaxf(c[mt][nt][3] + b1, 0.f);
            if (row < M) {
                __half2 h = __floats2half2_rn(v0, v1);
                *(__half2*)(out + (size_t)row * D + col) = h;
            }
            if (row + 8 < M) {
                __half2 h = __floats2half2_rn(v2, v3);
                *(__half2*)(out + (size_t)(row + 8) * D + col) = h;
            }
        }
    }
}

// ---------------------------------------------------------------------------
// Output layer: out[m, 0..3] = h[m,:] @ w_out^T + b_out.  One warp per row.
// ---------------------------------------------------------------------------
__global__ void k_out(const __half* __restrict__ h,
                      const float* __restrict__ w,
                      const float* __restrict__ b,
                      float* __restrict__ out, int M) {
    int gid  = blockIdx.x * blockDim.x + threadIdx.x;
    int row  = gid >> 5;
    int lane = gid & 31;
    if (row >= M) return;
    uint2 u = __ldg((const uint2*)h + (size_t)row * 32 + lane);
    __half2 h0 = *(__half2*)&u.x, h1 = *(__half2*)&u.y;
    float2 f0 = __half22float2(h0), f1 = __half22float2(h1);
    float r[4];
    #pragma unroll
    for (int o = 0; o < 4; ++o) {
        float4 wv = __ldg((const float4*)(w + o * D) + lane);
        float p = f0.x * wv.x + f0.y * wv.y + f1.x * wv.z + f1.y * wv.w;
        #pragma unroll
        for (int s = 16; s > 0; s >>= 1)
            p += __shfl_xor_sync(0xffffffffu, p, s);
        r[o] = p;
    }
    if (lane == 0) {
        *(float4*)(out + (size_t)row * 4) =
            make_float4(r[0] + b[0], r[1] + b[1], r[2] + b[2], r[3] + b[3]);
    }
}

// ---------------------------------------------------------------------------
extern "C" void kernel_launch(void* const* d_in, const int* in_sizes, int n_in,
                              void* d_out, int out_size) {
    const float* x     = (const float*)d_in[0];
    const int*   ei    = (const int*)  d_in[1];
    const float* w1_l  = (const float*)d_in[2];
    const float* b1_l  = (const float*)d_in[3];
    const float* w1_r  = (const float*)d_in[4];
    const float* w2_l  = (const float*)d_in[5];
    const float* b2_l  = (const float*)d_in[6];
    const float* w2_r  = (const float*)d_in[7];
    const float* w_out = (const float*)d_in[8];
    const float* b_out = (const float*)d_in[9];
    float*       out   = (float*)d_out;

    const int E    = in_sizes[1] / 2;
    const int* src = ei;
    const int* dst = ei + E;

    __half *xh, *agg, *h1, *h2, *wh;
    int *cnt, *rowstart, *cursor, *perm;
    cudaGetSymbolAddress((void**)&xh,       g_xh);
    cudaGetSymbolAddress((void**)&agg,      g_agg);
    cudaGetSymbolAddress((void**)&h1,       g_h1);
    cudaGetSymbolAddress((void**)&h2,       g_h2);
    cudaGetSymbolAddress((void**)&wh,       g_wh);
    cudaGetSymbolAddress((void**)&cnt,      g_cnt);
    cudaGetSymbolAddress((void**)&rowstart, g_rowstart);
    cudaGetSymbolAddress((void**)&cursor,   g_cursor);
    cudaGetSymbolAddress((void**)&perm,     g_perm);

    const __half* wh1l = wh;
    const __half* wh1r = wh + 16384;
    const __half* wh2l = wh + 32768;
    const __half* wh2r = wh + 49152;

    const int M      = N_NODES;
    const int n8     = M * D / 8;
    const int cu     = n8 + 8192;                 // convert units incl. weights
    const int prep_n = (E > cu) ? E : cu;
    const int prep_b = (prep_n + 255) / 256;
    const int eb     = (E + 255) / 256;
    const int gath_b = (M + 7) / 8;
    const int gemm_b = (M + 127) / 128;
    const int out_b  = (M * 32 + 255) / 256;

    // ---- setup ----
    k_prep   <<<prep_b, 256>>>(x, dst, w1_l, w1_r, w2_l, w2_r, xh, wh, cnt, E, n8);
    k_scan   <<<1, 1024>>>(cnt, rowstart, cursor, E);
    k_permute<<<eb, 256>>>(src, dst, cursor, perm, E);

    // ---- Layer 1 ----
    k_gather<<<gath_b, 256>>>(xh, perm, rowstart, agg);
    k_gemm  <<<gemm_b, 256>>>(agg, xh, wh1l, wh1r, b1_l, h1, M);

    // ---- Layer 2 ----
    k_gather<<<gath_b, 256>>>(h1, perm, rowstart, agg);
    k_gemm  <<<gemm_b, 256>>>(agg, h1, wh2l, wh2r, b2_l, h2, M);

    // ---- Output projection ----
    k_out<<<out_b, 256>>>(h2, w_out, b_out, out, M);
}